// round 13
// baseline (speedup 1.0000x reference)
#include <cuda_runtime.h>
#include <cuda_fp16.h>
#include <math.h>

#define NG 1024
#define SEM 768
#define NMAX 100000
#define EMAX 1250000
#define SCAN_B 512
#define SCAN_NB 196   // ceil(100000/512)
#define DEGB8 1221    // ceil(2*(EMAX/8)/256)

// ---------------- device scratch (static, allocation-free; zero at load) ----
__device__ int    g_deg   [2][NMAX];      // re-zeroed by k_pull2 after use
__device__ int    g_rowptr[2][NMAX];
__device__ int    g_cursor[2][NMAX];
__device__ int    g_aggv  [2][SCAN_NB];
__device__ int    g_flag  [2][SCAN_NB];   // re-zeroed by k_fill after scan
__device__ int    g_csr   [2][EMAX];
__device__ int    g_nd    [2][NMAX];      // packed {half(dinv):16 | ty:16}
__device__ float  g_dinv  [2][NMAX];      // exact per-node dinv (fp32)
__device__ uint4  g_tabh  [2][200 * 8];   // emb @ W1 table, fp16, 128B/row
__device__ uint4  g_x     [2][NMAX * 8];  // xd fp16: 64 halves = 8 x uint4 /node
__device__ float4 g_pool  [2][NG * 16];   // re-zeroed by k_epilogue after use

__device__ __forceinline__ void red_add_v4(float* addr, float4 v) {
    asm volatile("red.global.add.v4.f32 [%0], {%1, %2, %3, %4};"
                 :: "l"(addr), "f"(v.x), "f"(v.y), "f"(v.z), "f"(v.w)
                 : "memory");
}
__device__ __forceinline__ float4 ldg4(const float* p) {
    return __ldg((const float4*)p);
}

// ---------------- kernels ----------------

// launch 1: blocks [0,DEGB8) = in-degree atomics (8 edges/thread, 2x int4);
//           blocks [DEGB8, DEGB8+75) = fp16 tab build (4 rows each, 300 rows)
__global__ void k_degtab(const int* __restrict__ eA, const int* __restrict__ eC,
                         const float* __restrict__ embA, const float* __restrict__ W1A,
                         const float* __restrict__ embC, const float* __restrict__ W1C) {
    int b = blockIdx.x;
    if (b < DEGB8) {
        int t = b * 256 + threadIdx.x;
        const int Q = EMAX / 8;        // 156250
        if (t >= 2 * Q) return;
        int s = t >= Q; int e = t - s * Q;
        const int4* dst4 = (const int4*)((s ? eC : eA) + EMAX);
        int4 qa = __ldg(&dst4[2 * e]);
        int4 qb = __ldg(&dst4[2 * e + 1]);
        int* deg = g_deg[s];
        atomicAdd(&deg[qa.x], 1); atomicAdd(&deg[qa.y], 1);
        atomicAdd(&deg[qa.z], 1); atomicAdd(&deg[qa.w], 1);
        atomicAdd(&deg[qb.x], 1); atomicAdd(&deg[qb.y], 1);
        atomicAdd(&deg[qb.z], 1); atomicAdd(&deg[qb.w], 1);
    } else {
        __shared__ float sx[4][64];
        int sub = threadIdx.x >> 6, j = threadIdx.x & 63;
        int row = (b - DEGB8) * 4 + sub;   // 0..299 exactly
        const float* emb; const float* W; __half* tab; int rr;
        if (row < 200) { emb = embA; W = W1A; tab = (__half*)g_tabh[0]; rr = row; }
        else           { emb = embC; W = W1C; tab = (__half*)g_tabh[1]; rr = row - 200; }
        sx[sub][j] = emb[rr * 64 + j];
        __syncthreads();
        float acc = 0.f;
#pragma unroll
        for (int k = 0; k < 64; k++) acc = fmaf(sx[sub][k], W[k * 64 + j], acc);
        tab[rr * 64 + j] = __float2half(acc);
    }
}

// launch 2: single-pass scan (decoupled lookback; flags pre-zeroed).
// Finalizes rowptr/cursor, dinv (fp32), and packed nd.
__global__ void __launch_bounds__(SCAN_B) k_scan(const int* __restrict__ tyA,
                                                 const int* __restrict__ tyC) {
    int s = blockIdx.x >= SCAN_NB;
    int blk = blockIdx.x - s * SCAN_NB;
    int i = blk * SCAN_B + threadIdx.x;
    int val = (i < NMAX) ? g_deg[s][i] : 0;
    __shared__ int sm[SCAN_B];
    __shared__ int s_prefix;
    sm[threadIdx.x] = val;
    __syncthreads();
#pragma unroll
    for (int off = 1; off < SCAN_B; off <<= 1) {
        int t = (threadIdx.x >= off) ? sm[threadIdx.x - off] : 0;
        __syncthreads();
        sm[threadIdx.x] += t;
        __syncthreads();
    }
    int incl = sm[threadIdx.x];

    if (threadIdx.x < 32) {
        int lane = threadIdx.x;
        if (lane == 0) {
            g_aggv[s][blk] = sm[SCAN_B - 1];
            __threadfence();
            atomicExch(&g_flag[s][blk], 1);
        }
        int run = 0;
        for (int wbase = blk - 1; wbase >= 0; wbase -= 32) {
            int p = wbase - lane;
            int c = 0;
            if (p >= 0) {
                while (atomicAdd(&g_flag[s][p], 0) == 0) { }
                c = atomicAdd(&g_aggv[s][p], 0);
            }
#pragma unroll
            for (int m = 16; m > 0; m >>= 1)
                c += __shfl_xor_sync(0xFFFFFFFFu, c, m);
            run += c;
        }
        if (lane == 0) s_prefix = run;
    }
    __syncthreads();

    if (i < NMAX) {
        int r = s_prefix + incl - val;
        g_rowptr[s][i] = r;
        g_cursor[s][i] = r;
        float dv = rsqrtf((float)val + 1.0f);
        g_dinv[s][i] = dv;
        int ty = __ldg((s ? tyC : tyA) + i);
        unsigned short dh = __half_as_ushort(__float2half_rn(dv));
        g_nd[s][i] = ty | ((int)dh << 16);
    }
}

// launch 3: CSR fill (8 edges/thread, 2x int4) + re-zero scan flags
__global__ void k_fill(const int* __restrict__ eA, const int* __restrict__ eC) {
    int t = blockIdx.x * blockDim.x + threadIdx.x;
    if (t < SCAN_NB) { g_flag[0][t] = 0; g_flag[1][t] = 0; }
    const int Q = EMAX / 8;
    if (t >= 2 * Q) return;
    int s = t >= Q; int e = t - s * Q;
    const int* edge = s ? eC : eA;
    int4 us0 = __ldg((const int4*)edge + 2 * e);
    int4 us1 = __ldg((const int4*)edge + 2 * e + 1);
    int4 vs0 = __ldg((const int4*)(edge + EMAX) + 2 * e);
    int4 vs1 = __ldg((const int4*)(edge + EMAX) + 2 * e + 1);
    int* cur = g_cursor[s];
    int* csr = g_csr[s];
    csr[atomicAdd(&cur[vs0.x], 1)] = us0.x;
    csr[atomicAdd(&cur[vs0.y], 1)] = us0.y;
    csr[atomicAdd(&cur[vs0.z], 1)] = us0.z;
    csr[atomicAdd(&cur[vs0.w], 1)] = us0.w;
    csr[atomicAdd(&cur[vs1.x], 1)] = us1.x;
    csr[atomicAdd(&cur[vs1.y], 1)] = us1.y;
    csr[atomicAdd(&cur[vs1.z], 1)] = us1.z;
    csr[atomicAdd(&cur[vs1.w], 1)] = us1.w;
}

// launch 4 (ncu capture slot): pull layer 1, fp16 tab + HFMA2,
// phase-batched inner loop: 4 nd loads -> 4 tab loads -> 16 HFMA2.
__global__ void __launch_bounds__(256) k_pull1(const float* __restrict__ b1A,
                                               const float* __restrict__ b1C) {
    int blk = blockIdx.x;              // 6250 blocks: 3125 per graph
    int s = blk >= 3125;
    int v = (blk - s * 3125) * 32 + (threadIdx.x >> 3);
    int l = threadIdx.x & 7;           // feature chunk: halves [8l, 8l+8)
    const uint4* __restrict__ tab = g_tabh[s];
    const int* __restrict__ nd = g_nd[s];

    float dv = __ldg(&g_dinv[s][v]);
    __half2 za0, za1, za2, za3, zb0, zb1, zb2, zb3;
    {
        int nv = __ldg(&nd[v]);
        uint4 tq = __ldg(&tab[(nv & 0xFFFF) * 8 + l]);
        __half2 d2 = __float2half2_rn(dv);
        __half2* th = reinterpret_cast<__half2*>(&tq);
        za0 = __hmul2(th[0], d2); za1 = __hmul2(th[1], d2);
        za2 = __hmul2(th[2], d2); za3 = __hmul2(th[3], d2);
        __half2 z = __float2half2_rn(0.f);
        zb0 = z; zb1 = z; zb2 = z; zb3 = z;
    }

    int r = g_rowptr[s][v], d = g_deg[s][v];
    const int* __restrict__ cs = g_csr[s] + r;

#define NBA(u) do { \
        int n_ = __ldg(&nd[(u)]); \
        uint4 t_ = __ldg(&tab[(n_ & 0xFFFF) * 8 + l]); \
        __half2 d_ = __half2half2(__ushort_as_half((unsigned short)((unsigned)n_ >> 16))); \
        __half2* th_ = reinterpret_cast<__half2*>(&t_); \
        za0 = __hfma2(th_[0], d_, za0); za1 = __hfma2(th_[1], d_, za1); \
        za2 = __hfma2(th_[2], d_, za2); za3 = __hfma2(th_[3], d_, za3); \
    } while (0)

    int k = 0;
    int pe = (4 - (r & 3)) & 3; if (pe > d) pe = d;
    for (; k < pe; k++) NBA(__ldg(cs + k));
    for (; k + 4 <= d; k += 4) {
        int4 q = __ldg((const int4*)(cs + k));
        // phase 1: all nd loads in flight
        int n0 = __ldg(&nd[q.x]);
        int n1 = __ldg(&nd[q.y]);
        int n2 = __ldg(&nd[q.z]);
        int n3 = __ldg(&nd[q.w]);
        // phase 2: all tab loads in flight
        uint4 t0 = __ldg(&tab[(n0 & 0xFFFF) * 8 + l]);
        uint4 t1 = __ldg(&tab[(n1 & 0xFFFF) * 8 + l]);
        uint4 t2 = __ldg(&tab[(n2 & 0xFFFF) * 8 + l]);
        uint4 t3 = __ldg(&tab[(n3 & 0xFFFF) * 8 + l]);
        // phase 3: FMAs, two accumulator banks
        __half2 d0 = __half2half2(__ushort_as_half((unsigned short)((unsigned)n0 >> 16)));
        __half2 d1 = __half2half2(__ushort_as_half((unsigned short)((unsigned)n1 >> 16)));
        __half2 d2 = __half2half2(__ushort_as_half((unsigned short)((unsigned)n2 >> 16)));
        __half2 d3 = __half2half2(__ushort_as_half((unsigned short)((unsigned)n3 >> 16)));
        __half2* h0 = reinterpret_cast<__half2*>(&t0);
        __half2* h1 = reinterpret_cast<__half2*>(&t1);
        __half2* h2 = reinterpret_cast<__half2*>(&t2);
        __half2* h3 = reinterpret_cast<__half2*>(&t3);
        za0 = __hfma2(h0[0], d0, za0); za1 = __hfma2(h0[1], d0, za1);
        za2 = __hfma2(h0[2], d0, za2); za3 = __hfma2(h0[3], d0, za3);
        zb0 = __hfma2(h1[0], d1, zb0); zb1 = __hfma2(h1[1], d1, zb1);
        zb2 = __hfma2(h1[2], d1, zb2); zb3 = __hfma2(h1[3], d1, zb3);
        za0 = __hfma2(h2[0], d2, za0); za1 = __hfma2(h2[1], d2, za1);
        za2 = __hfma2(h2[2], d2, za2); za3 = __hfma2(h2[3], d2, za3);
        zb0 = __hfma2(h3[0], d3, zb0); zb1 = __hfma2(h3[1], d3, zb1);
        zb2 = __hfma2(h3[2], d3, zb2); zb3 = __hfma2(h3[3], d3, zb3);
    }
    for (; k < d; k++) NBA(__ldg(cs + k));
#undef NBA

    float2 f0 = __half22float2(__hadd2(za0, zb0));
    float2 f1 = __half22float2(__hadd2(za1, zb1));
    float2 f2 = __half22float2(__hadd2(za2, zb2));
    float2 f3 = __half22float2(__hadd2(za3, zb3));

    const float* b1 = s ? b1C : b1A;
    float4 b0 = ldg4(b1 + l * 8), b1v = ldg4(b1 + l * 8 + 4);
    float x0 = dv * fmaxf(fmaf(dv, f0.x, b0.x), 0.f);
    float x1 = dv * fmaxf(fmaf(dv, f0.y, b0.y), 0.f);
    float x2 = dv * fmaxf(fmaf(dv, f1.x, b0.z), 0.f);
    float x3 = dv * fmaxf(fmaf(dv, f1.y, b0.w), 0.f);
    float x4 = dv * fmaxf(fmaf(dv, f2.x, b1v.x), 0.f);
    float x5 = dv * fmaxf(fmaf(dv, f2.y, b1v.y), 0.f);
    float x6 = dv * fmaxf(fmaf(dv, f3.x, b1v.z), 0.f);
    float x7 = dv * fmaxf(fmaf(dv, f3.y, b1v.w), 0.f);
    __half2 h0 = __floats2half2_rn(x0, x1);
    __half2 h1 = __floats2half2_rn(x2, x3);
    __half2 h2 = __floats2half2_rn(x4, x5);
    __half2 h3 = __floats2half2_rn(x6, x7);
    uint4 u;
    u.x = *reinterpret_cast<unsigned int*>(&h0);
    u.y = *reinterpret_cast<unsigned int*>(&h1);
    u.z = *reinterpret_cast<unsigned int*>(&h2);
    u.w = *reinterpret_cast<unsigned int*>(&h3);
    g_x[s][v * 8 + l] = u;
}

// launch 5: pull layer 2 + segmented pooling (HADD2, unroll 8) +
// re-zero this block's g_deg entries for the next call.
__global__ void __launch_bounds__(256) k_pull2(const int* __restrict__ batchA,
                                               const int* __restrict__ batchC) {
    int blk = blockIdx.x;              // 6250 blocks: 3125 per graph
    int s = blk >= 3125;
    int v0 = (blk - s * 3125) * 32;
    int li = threadIdx.x >> 3;         // local node 0..31
    int l  = threadIdx.x & 7;          // feature chunk 0..7
    int v = v0 + li;

    const uint4* __restrict__ xd4 = (const uint4*)g_x[s];
    __half2 z = __float2half2_rn(0.f);
    __half2 ha0 = z, ha1 = z, ha2 = z, ha3 = z;
    __half2 hb0 = z, hb1 = z, hb2 = z, hb3 = z;

#define ACCA(q) do { __half2* h_ = reinterpret_cast<__half2*>(&(q)); \
        ha0 = __hadd2(ha0, h_[0]); ha1 = __hadd2(ha1, h_[1]); \
        ha2 = __hadd2(ha2, h_[2]); ha3 = __hadd2(ha3, h_[3]); } while (0)
#define ACCB(q) do { __half2* h_ = reinterpret_cast<__half2*>(&(q)); \
        hb0 = __hadd2(hb0, h_[0]); hb1 = __hadd2(hb1, h_[1]); \
        hb2 = __hadd2(hb2, h_[2]); hb3 = __hadd2(hb3, h_[3]); } while (0)

    uint4 qs = __ldg(&xd4[v * 8 + l]);   // self term
    ACCA(qs);
    int r = g_rowptr[s][v], d = g_deg[s][v];
    const int* __restrict__ cs = g_csr[s] + r;
    int k = 0;
    int pe = (4 - (r & 3)) & 3; if (pe > d) pe = d;
    for (; k < pe; k++) { uint4 q = __ldg(&xd4[__ldg(cs + k) * 8 + l]); ACCB(q); }
    for (; k + 8 <= d; k += 8) {
        int4 qa = __ldg((const int4*)(cs + k));
        int4 qb = __ldg((const int4*)(cs + k + 4));
        uint4 q0 = __ldg(&xd4[qa.x * 8 + l]);
        uint4 q1 = __ldg(&xd4[qa.y * 8 + l]);
        uint4 q2 = __ldg(&xd4[qa.z * 8 + l]);
        uint4 q3 = __ldg(&xd4[qa.w * 8 + l]);
        uint4 q4 = __ldg(&xd4[qb.x * 8 + l]);
        uint4 q5 = __ldg(&xd4[qb.y * 8 + l]);
        uint4 q6 = __ldg(&xd4[qb.z * 8 + l]);
        uint4 q7 = __ldg(&xd4[qb.w * 8 + l]);
        ACCA(q0); ACCB(q1); ACCA(q2); ACCB(q3);
        ACCA(q4); ACCB(q5); ACCA(q6); ACCB(q7);
    }
    for (; k + 4 <= d; k += 4) {
        int4 q = __ldg((const int4*)(cs + k));
        uint4 q0 = __ldg(&xd4[q.x * 8 + l]);
        uint4 q1 = __ldg(&xd4[q.y * 8 + l]);
        uint4 q2 = __ldg(&xd4[q.z * 8 + l]);
        uint4 q3 = __ldg(&xd4[q.w * 8 + l]);
        ACCA(q0); ACCB(q1); ACCA(q2); ACCB(q3);
    }
    for (; k < d; k++) { uint4 q = __ldg(&xd4[__ldg(cs + k) * 8 + l]); ACCA(q); }
#undef ACCA
#undef ACCB

    float2 p0 = __half22float2(__hadd2(ha0, hb0));
    float2 p1 = __half22float2(__hadd2(ha1, hb1));
    float2 p2 = __half22float2(__hadd2(ha2, hb2));
    float2 p3 = __half22float2(__hadd2(ha3, hb3));
    float dv = __ldg(&g_dinv[s][v]);

    __shared__ float sp[32][68];   // padded to break bank conflicts
    __shared__ int   sb[32];
    sp[li][l * 8 + 0] = p0.x * dv; sp[li][l * 8 + 1] = p0.y * dv;
    sp[li][l * 8 + 2] = p1.x * dv; sp[li][l * 8 + 3] = p1.y * dv;
    sp[li][l * 8 + 4] = p2.x * dv; sp[li][l * 8 + 5] = p2.y * dv;
    sp[li][l * 8 + 6] = p3.x * dv; sp[li][l * 8 + 7] = p3.y * dv;
    if (threadIdx.x < 32)
        sb[threadIdx.x] = __ldg((s ? batchC : batchA) + v0 + threadIdx.x);
    __syncthreads();

    // all reads of g_deg for this block's nodes are done -> re-zero for next call
    if (threadIdx.x < 32) g_deg[s][v0 + threadIdx.x] = 0;

    int gId = sb[li];
    bool head = (li == 0) || (sb[li - 1] != gId);
    if (head) {
        int len = 1;
        while (li + len < 32 && sb[li + len] == gId) len++;
        float t0 = 0, t1 = 0, t2 = 0, t3 = 0, t4 = 0, t5 = 0, t6 = 0, t7 = 0;
        for (int j = li; j < li + len; j++) {
            t0 += sp[j][l * 8 + 0]; t1 += sp[j][l * 8 + 1];
            t2 += sp[j][l * 8 + 2]; t3 += sp[j][l * 8 + 3];
            t4 += sp[j][l * 8 + 4]; t5 += sp[j][l * 8 + 5];
            t6 += sp[j][l * 8 + 6]; t7 += sp[j][l * 8 + 7];
        }
        float* dst = (float*)&g_pool[s][gId * 16];
        red_add_v4(dst + l * 8,     make_float4(t0, t1, t2, t3));
        red_add_v4(dst + l * 8 + 4, make_float4(t4, t5, t6, t7));
    }
}

// count of nodes with batch==g in sorted array (two binary searches)
__device__ __forceinline__ int cnt_graph(const int* __restrict__ b, int g) {
    int lo = 0, hi = NMAX;
    while (lo < hi) { int m = (lo + hi) >> 1; if (__ldg(b + m) < g) lo = m + 1; else hi = m; }
    int lb = lo;
    lo = 0; hi = NMAX;
    while (lo < hi) { int m = (lo + hi) >> 1; if (__ldg(b + m) <= g) lo = m + 1; else hi = m; }
    return lo - lb;
}

// launch 6: epilogue (8 graphs/block, 16 lanes x 4 cols) + re-zero pool.
__global__ void __launch_bounds__(128) k_epilogue(
    const float* __restrict__ sem,
    const int* __restrict__ batchA, const int* __restrict__ batchC,
    const float* __restrict__ W2A, const float* __restrict__ b2A,
    const float* __restrict__ W2C, const float* __restrict__ b2C,
    const float* __restrict__ Wg1, const float* __restrict__ bg1,
    const float* __restrict__ Wsem, const float* __restrict__ bsem,
    const float* __restrict__ Wg2, const float* __restrict__ bg2,
    const float* __restrict__ ln_g, const float* __restrict__ ln_b,
    const float* __restrict__ Wc, const float* __restrict__ bc,
    float* __restrict__ out) {
    int sg = threadIdx.x >> 4;     // subgroup 0..7 (one graph each)
    int l  = threadIdx.x & 15;
    int g  = blockIdx.x * 8 + sg;
    int j0 = l * 4;

    __shared__ float sPA[8][64], sPC[8][64];
    __shared__ float sA [8][64], sB [8][64];
    __shared__ float sHS[8][64], sHM[8][64];

    float4 PA = g_pool[0][g * 16 + l];
    float4 PC = g_pool[1][g * 16 + l];
    g_pool[0][g * 16 + l] = make_float4(0.f, 0.f, 0.f, 0.f);   // restore for next call
    g_pool[1][g * 16 + l] = make_float4(0.f, 0.f, 0.f, 0.f);
    *(float4*)&sPA[sg][j0] = PA;
    *(float4*)&sPC[sg][j0] = PC;
    float cntA = (float)cnt_graph(batchA, g);
    float cntC = (float)cnt_graph(batchC, g);
    __syncwarp();

    float4 a = make_float4(0.f, 0.f, 0.f, 0.f);
    float4 b = make_float4(0.f, 0.f, 0.f, 0.f);
#pragma unroll 4
    for (int k = 0; k < 64; k++) {
        float pa = sPA[sg][k], pc = sPC[sg][k];
        float4 wa = ldg4(W2A + k * 64 + j0);
        float4 wc = ldg4(W2C + k * 64 + j0);
        a.x = fmaf(pa, wa.x, a.x); a.y = fmaf(pa, wa.y, a.y);
        a.z = fmaf(pa, wa.z, a.z); a.w = fmaf(pa, wa.w, a.w);
        b.x = fmaf(pc, wc.x, b.x); b.y = fmaf(pc, wc.y, b.y);
        b.z = fmaf(pc, wc.z, b.z); b.w = fmaf(pc, wc.w, b.w);
    }
    {
        float4 ba = ldg4(b2A + j0), bb = ldg4(b2C + j0);
        a.x = fmaf(cntA, ba.x, a.x); a.y = fmaf(cntA, ba.y, a.y);
        a.z = fmaf(cntA, ba.z, a.z); a.w = fmaf(cntA, ba.w, a.w);
        b.x = fmaf(cntC, bb.x, b.x); b.y = fmaf(cntC, bb.y, b.y);
        b.z = fmaf(cntC, bb.z, b.z); b.w = fmaf(cntC, bb.w, b.w);
    }
    *(float4*)&sA[sg][j0] = a;
    *(float4*)&sB[sg][j0] = b;
    __syncwarp();

    // gate 1
    float4 acc = ldg4(bg1 + j0);
#pragma unroll 4
    for (int k = 0; k < 64; k++) {
        float va = sA[sg][k];
        float4 w = ldg4(Wg1 + k * 64 + j0);
        acc.x = fmaf(va, w.x, acc.x); acc.y = fmaf(va, w.y, acc.y);
        acc.z = fmaf(va, w.z, acc.z); acc.w = fmaf(va, w.w, acc.w);
    }
#pragma unroll 4
    for (int k = 0; k < 64; k++) {
        float vb = sB[sg][k];
        float4 w = ldg4(Wg1 + (64 + k) * 64 + j0);
        acc.x = fmaf(vb, w.x, acc.x); acc.y = fmaf(vb, w.y, acc.y);
        acc.z = fmaf(vb, w.z, acc.z); acc.w = fmaf(vb, w.w, acc.w);
    }
    float4 g1;
    g1.x = 1.f / (1.f + expf(-acc.x));
    g1.y = 1.f / (1.f + expf(-acc.y));
    g1.z = 1.f / (1.f + expf(-acc.z));
    g1.w = 1.f / (1.f + expf(-acc.w));
    float4 hst;
    hst.x = g1.x * a.x + (1.f - g1.x) * b.x;
    hst.y = g1.y * a.y + (1.f - g1.y) * b.y;
    hst.z = g1.z * a.z + (1.f - g1.z) * b.z;
    hst.w = g1.w * a.w + (1.f - g1.w) * b.w;

    // sem projection
    float4 ac2 = ldg4(bsem + j0);
    const float* semrow = sem + g * SEM;
#pragma unroll 4
    for (int k = 0; k < SEM; k += 4) {
        float4 s4 = ldg4(semrow + k);
        float4 w0 = ldg4(Wsem + (k + 0) * 64 + j0);
        float4 w1 = ldg4(Wsem + (k + 1) * 64 + j0);
        float4 w2 = ldg4(Wsem + (k + 2) * 64 + j0);
        float4 w3 = ldg4(Wsem + (k + 3) * 64 + j0);
        ac2.x = fmaf(s4.x, w0.x, ac2.x); ac2.y = fmaf(s4.x, w0.y, ac2.y);
        ac2.z = fmaf(s4.x, w0.z, ac2.z); ac2.w = fmaf(s4.x, w0.w, ac2.w);
        ac2.x = fmaf(s4.y, w1.x, ac2.x); ac2.y = fmaf(s4.y, w1.y, ac2.y);
        ac2.z = fmaf(s4.y, w1.z, ac2.z); ac2.w = fmaf(s4.y, w1.w, ac2.w);
        ac2.x = fmaf(s4.z, w2.x, ac2.x); ac2.y = fmaf(s4.z, w2.y, ac2.y);
        ac2.z = fmaf(s4.z, w2.z, ac2.z); ac2.w = fmaf(s4.z, w2.w, ac2.w);
        ac2.x = fmaf(s4.w, w3.x, ac2.x); ac2.y = fmaf(s4.w, w3.y, ac2.y);
        ac2.z = fmaf(s4.w, w3.z, ac2.z); ac2.w = fmaf(s4.w, w3.w, ac2.w);
    }
    float4 hm;
    hm.x = fmaxf(ac2.x, 0.f); hm.y = fmaxf(ac2.y, 0.f);
    hm.z = fmaxf(ac2.z, 0.f); hm.w = fmaxf(ac2.w, 0.f);

    *(float4*)&sHS[sg][j0] = hst;
    *(float4*)&sHM[sg][j0] = hm;
    __syncwarp();

    // gate 2
    float4 ac3 = ldg4(bg2 + j0);
#pragma unroll 4
    for (int k = 0; k < 64; k++) {
        float vh = sHS[sg][k];
        float4 w = ldg4(Wg2 + k * 64 + j0);
        ac3.x = fmaf(vh, w.x, ac3.x); ac3.y = fmaf(vh, w.y, ac3.y);
        ac3.z = fmaf(vh, w.z, ac3.z); ac3.w = fmaf(vh, w.w, ac3.w);
    }
#pragma unroll 4
    for (int k = 0; k < 64; k++) {
        float vm = sHM[sg][k];
        float4 w = ldg4(Wg2 + (64 + k) * 64 + j0);
        ac3.x = fmaf(vm, w.x, ac3.x); ac3.y = fmaf(vm, w.y, ac3.y);
        ac3.z = fmaf(vm, w.z, ac3.z); ac3.w = fmaf(vm, w.w, ac3.w);
    }
    float4 g2;
    g2.x = 1.f / (1.f + expf(-ac3.x));
    g2.y = 1.f / (1.f + expf(-ac3.y));
    g2.z = 1.f / (1.f + expf(-ac3.z));
    g2.w = 1.f / (1.f + expf(-ac3.w));
    float4 h;
    h.x = g2.x * hst.x + (1.f - g2.x) * hm.x;
    h.y = g2.y * hst.y + (1.f - g2.y) * hm.y;
    h.z = g2.z * hst.z + (1.f - g2.z) * hm.z;
    h.w = g2.w * hst.w + (1.f - g2.w) * hm.w;

    // layernorm over 64 (16-lane shfl reduce)
    float s1 = (h.x + h.y) + (h.z + h.w);
    float s2 = (h.x * h.x + h.y * h.y) + (h.z * h.z + h.w * h.w);
#pragma unroll
    for (int m = 1; m < 16; m <<= 1) {
        s1 += __shfl_xor_sync(0xFFFFFFFFu, s1, m);
        s2 += __shfl_xor_sync(0xFFFFFFFFu, s2, m);
    }
    float mu  = s1 * (1.f / 64.f);
    float var = s2 * (1.f / 64.f) - mu * mu;
    float rstd = rsqrtf(var + 1e-5f);
    float4 lg = ldg4(ln_g + j0), lb = ldg4(ln_b + j0);
    float4 hn;
    hn.x = (h.x - mu) * rstd * lg.x + lb.x;
    hn.y = (h.y - mu) * rstd * lg.y + lb.y;
    hn.z = (h.z - mu) * rstd * lg.z + lb.z;
    hn.w = (h.w - mu) * rstd * lg.w + lb.w;

    // classifier (NCLS=2): Wc is [64,2]
    float4 wc0 = ldg4(Wc + j0 * 2);
    float4 wc1 = ldg4(Wc + j0 * 2 + 4);
    float o0 = hn.x * wc0.x + hn.y * wc0.z + hn.z * wc1.x + hn.w * wc1.z;
    float o1 = hn.x * wc0.y + hn.y * wc0.w + hn.z * wc1.y + hn.w * wc1.w;
#pragma unroll
    for (int m = 1; m < 16; m <<= 1) {
        o0 += __shfl_xor_sync(0xFFFFFFFFu, o0, m);
        o1 += __shfl_xor_sync(0xFFFFFFFFu, o1, m);
    }
    if (l == 0) {
        out[g * 2 + 0] = o0 + __ldg(bc + 0);
        out[g * 2 + 1] = o1 + __ldg(bc + 1);
    }
}

// ---------------- launch ----------------
extern "C" void kernel_launch(void* const* d_in, const int* in_sizes, int n_in,
                              void* d_out, int out_size) {
    const int*   ast_type  = (const int*)  d_in[0];
    const int*   ast_edge  = (const int*)  d_in[1];
    const int*   ast_batch = (const int*)  d_in[2];
    const int*   cfg_type  = (const int*)  d_in[3];
    const int*   cfg_edge  = (const int*)  d_in[4];
    const int*   cfg_batch = (const int*)  d_in[5];
    const float* sem       = (const float*)d_in[6];
    const float* ast_emb   = (const float*)d_in[7];
    const float* cfg_emb   = (const float*)d_in[8];
    const float* ast_W1    = (const float*)d_in[9];
    const float* ast_b1    = (const float*)d_in[10];
    const float* ast_W2    = (const float*)d_in[11];
    const float* ast_b2    = (const float*)d_in[12];
    const float* cfg_W1    = (const float*)d_in[13];
    const float* cfg_b1    = (const float*)d_in[14];
    const float* cfg_W2    = (const float*)d_in[15];
    const float* cfg_b2    = (const float*)d_in[16];
    const float* Wg1       = (const float*)d_in[17];
    const float* bg1       = (const float*)d_in[18];
    const float* Wsem      = (const float*)d_in[19];
    const float* bsem      = (const float*)d_in[20];
    const float* Wg2       = (const float*)d_in[21];
    const float* bg2       = (const float*)d_in[22];
    const float* ln_g      = (const float*)d_in[23];
    const float* ln_b      = (const float*)d_in[24];
    const float* Wc        = (const float*)d_in[25];
    const float* bc        = (const float*)d_in[26];
    float* out = (float*)d_out;

    k_degtab<<<DEGB8 + 75, 256>>>(ast_edge, cfg_edge,
                                  ast_emb, ast_W1, cfg_emb, cfg_W1);
    k_scan<<<2 * SCAN_NB, SCAN_B>>>(ast_type, cfg_type);
    k_fill<<<DEGB8, 256>>>(ast_edge, cfg_edge);

    k_pull1<<<2 * NMAX / 32, 256>>>(ast_b1, cfg_b1);   // <- ncu capture slot 4
    k_pull2<<<2 * NMAX / 32, 256>>>(ast_batch, cfg_batch);

    k_epilogue<<<NG / 8, 128>>>(sem, ast_batch, cfg_batch,
                                ast_W2, ast_b2, cfg_W2, cfg_b2,
                                Wg1, bg1, Wsem, bsem, Wg2, bg2,
                                ln_g, ln_b, Wc, bc, out);
}

// round 15
// speedup vs baseline: 1.1607x; 1.1607x over previous
#include <cuda_runtime.h>
#include <cuda_fp16.h>
#include <math.h>

#define NG 1024
#define SEM 768
#define NMAX 100000
#define EMAX 1250000
#define CSRSZ (EMAX + 3 * NMAX + 4)
#define SCAN_B 512
#define SCAN_NB 196   // ceil(100000/512)
#define DEGB8 1221    // ceil(2*(EMAX/8)/256)

// ---------------- device scratch (static, allocation-free; zero at load) ----
__device__ int    g_deg   [2][NMAX];        // re-zeroed by k_pull2 after use
__device__ int    g_rowptr[2][NMAX];
__device__ int    g_cursor[2][NMAX];
__device__ int    g_aggv  [2][SCAN_NB];
__device__ int    g_flag  [2][SCAN_NB];     // re-zeroed by k_fill after scan
__device__ int    g_csr   [2][CSRSZ];
__device__ int    g_nd    [2][NMAX + 1];    // packed {half(dinv):16 | ty:16}; [NMAX]=0 ghost
__device__ float  g_dinv  [2][NMAX];        // exact per-node dinv (fp32)
__device__ uint4  g_tabh  [2][200 * 8];     // emb @ W1 table, fp16, 128B/row
__device__ uint4  g_x     [2][(NMAX + 1) * 8]; // xd fp16; row NMAX = zeros (ghost)
__device__ float4 g_pool  [2][NG * 16];     // re-zeroed by k_epilogue after use

__device__ __forceinline__ void red_add_v4(float* addr, float4 v) {
    asm volatile("red.global.add.v4.f32 [%0], {%1, %2, %3, %4};"
                 :: "l"(addr), "f"(v.x), "f"(v.y), "f"(v.z), "f"(v.w)
                 : "memory");
}
__device__ __forceinline__ float4 ldg4(const float* p) {
    return __ldg((const float4*)p);
}

// ---------------- kernels ----------------

// launch 1: blocks [0,DEGB8) = in-degree atomics (8 edges/thread, 2x int4);
//           blocks [DEGB8, DEGB8+75) = fp16 tab build (4 rows each, 300 rows)
__global__ void k_degtab(const int* __restrict__ eA, const int* __restrict__ eC,
                         const float* __restrict__ embA, const float* __restrict__ W1A,
                         const float* __restrict__ embC, const float* __restrict__ W1C) {
    int b = blockIdx.x;
    if (b < DEGB8) {
        int t = b * 256 + threadIdx.x;
        const int Q = EMAX / 8;        // 156250
        if (t >= 2 * Q) return;
        int s = t >= Q; int e = t - s * Q;
        const int4* dst4 = (const int4*)((s ? eC : eA) + EMAX);
        int4 qa = __ldg(&dst4[2 * e]);
        int4 qb = __ldg(&dst4[2 * e + 1]);
        int* deg = g_deg[s];
        atomicAdd(&deg[qa.x], 1); atomicAdd(&deg[qa.y], 1);
        atomicAdd(&deg[qa.z], 1); atomicAdd(&deg[qa.w], 1);
        atomicAdd(&deg[qb.x], 1); atomicAdd(&deg[qb.y], 1);
        atomicAdd(&deg[qb.z], 1); atomicAdd(&deg[qb.w], 1);
    } else {
        __shared__ float sx[4][64];
        int sub = threadIdx.x >> 6, j = threadIdx.x & 63;
        int row = (b - DEGB8) * 4 + sub;   // 0..299 exactly
        const float* emb; const float* W; __half* tab; int rr;
        if (row < 200) { emb = embA; W = W1A; tab = (__half*)g_tabh[0]; rr = row; }
        else           { emb = embC; W = W1C; tab = (__half*)g_tabh[1]; rr = row - 200; }
        sx[sub][j] = emb[rr * 64 + j];
        __syncthreads();
        float acc = 0.f;
#pragma unroll
        for (int k = 0; k < 64; k++) acc = fmaf(sx[sub][k], W[k * 64 + j], acc);
        tab[rr * 64 + j] = __float2half(acc);
    }
}

// launch 2: single-pass scan over PADDED degrees (dpad = round-up-4).
// Finalizes 4-aligned rowptr/cursor, dinv, packed nd, and writes the
// sentinel (ghost = NMAX) padding slots in csr.
__global__ void __launch_bounds__(SCAN_B) k_scan(const int* __restrict__ tyA,
                                                 const int* __restrict__ tyC) {
    int s = blockIdx.x >= SCAN_NB;
    int blk = blockIdx.x - s * SCAN_NB;
    int i = blk * SCAN_B + threadIdx.x;
    int val = (i < NMAX) ? g_deg[s][i] : 0;
    int dpad = (val + 3) & ~3;
    __shared__ int sm[SCAN_B];
    __shared__ int s_prefix;
    sm[threadIdx.x] = dpad;
    __syncthreads();
#pragma unroll
    for (int off = 1; off < SCAN_B; off <<= 1) {
        int t = (threadIdx.x >= off) ? sm[threadIdx.x - off] : 0;
        __syncthreads();
        sm[threadIdx.x] += t;
        __syncthreads();
    }
    int incl = sm[threadIdx.x];

    if (threadIdx.x < 32) {
        int lane = threadIdx.x;
        if (lane == 0) {
            g_aggv[s][blk] = sm[SCAN_B - 1];
            __threadfence();
            atomicExch(&g_flag[s][blk], 1);
        }
        int run = 0;
        for (int wbase = blk - 1; wbase >= 0; wbase -= 32) {
            int p = wbase - lane;
            int c = 0;
            if (p >= 0) {
                while (atomicAdd(&g_flag[s][p], 0) == 0) { }
                c = atomicAdd(&g_aggv[s][p], 0);
            }
#pragma unroll
            for (int m = 16; m > 0; m >>= 1)
                c += __shfl_xor_sync(0xFFFFFFFFu, c, m);
            run += c;
        }
        if (lane == 0) s_prefix = run;
    }
    __syncthreads();

    if (i < NMAX) {
        int r = s_prefix + incl - dpad;   // 4-aligned exclusive prefix
        g_rowptr[s][i] = r;
        g_cursor[s][i] = r;
        float dv = rsqrtf((float)val + 1.0f);
        g_dinv[s][i] = dv;
        int ty = __ldg((s ? tyC : tyA) + i);
        unsigned short dh = __half_as_ushort(__float2half_rn(dv));
        g_nd[s][i] = ty | ((int)dh << 16);
        for (int p = val; p < dpad; p++) g_csr[s][r + p] = NMAX;  // ghost padding
    }
}

// launch 3: CSR fill (8 edges/thread, 2x int4) + re-zero scan flags
__global__ void k_fill(const int* __restrict__ eA, const int* __restrict__ eC) {
    int t = blockIdx.x * blockDim.x + threadIdx.x;
    if (t < SCAN_NB) { g_flag[0][t] = 0; g_flag[1][t] = 0; }
    const int Q = EMAX / 8;
    if (t >= 2 * Q) return;
    int s = t >= Q; int e = t - s * Q;
    const int* edge = s ? eC : eA;
    int4 us0 = __ldg((const int4*)edge + 2 * e);
    int4 us1 = __ldg((const int4*)edge + 2 * e + 1);
    int4 vs0 = __ldg((const int4*)(edge + EMAX) + 2 * e);
    int4 vs1 = __ldg((const int4*)(edge + EMAX) + 2 * e + 1);
    int* cur = g_cursor[s];
    int* csr = g_csr[s];
    csr[atomicAdd(&cur[vs0.x], 1)] = us0.x;
    csr[atomicAdd(&cur[vs0.y], 1)] = us0.y;
    csr[atomicAdd(&cur[vs0.z], 1)] = us0.z;
    csr[atomicAdd(&cur[vs0.w], 1)] = us0.w;
    csr[atomicAdd(&cur[vs1.x], 1)] = us1.x;
    csr[atomicAdd(&cur[vs1.y], 1)] = us1.y;
    csr[atomicAdd(&cur[vs1.z], 1)] = us1.z;
    csr[atomicAdd(&cur[vs1.w], 1)] = us1.w;
}

// launch 4 (ncu capture slot): pull layer 1, fp16 tab + HFMA2,
// interleaved dual-bank loop (R12 form), uniform 4-wide over padded rows.
__global__ void __launch_bounds__(256) k_pull1(const float* __restrict__ b1A,
                                               const float* __restrict__ b1C) {
    int blk = blockIdx.x;              // 6250 blocks: 3125 per graph
    int s = blk >= 3125;
    int v = (blk - s * 3125) * 32 + (threadIdx.x >> 3);
    int l = threadIdx.x & 7;           // feature chunk: halves [8l, 8l+8)
    const uint4* __restrict__ tab = g_tabh[s];
    const int* __restrict__ nd = g_nd[s];

    float dv = __ldg(&g_dinv[s][v]);
    __half2 za0, za1, za2, za3, zb0, zb1, zb2, zb3;
    {
        int nv = __ldg(&nd[v]);
        uint4 tq = __ldg(&tab[(nv & 0xFFFF) * 8 + l]);
        __half2 d2 = __float2half2_rn(dv);
        __half2* th = reinterpret_cast<__half2*>(&tq);
        za0 = __hmul2(th[0], d2); za1 = __hmul2(th[1], d2);
        za2 = __hmul2(th[2], d2); za3 = __hmul2(th[3], d2);
        __half2 z = __float2half2_rn(0.f);
        zb0 = z; zb1 = z; zb2 = z; zb3 = z;
    }

    int r = g_rowptr[s][v], d = g_deg[s][v];
    int dpad = (d + 3) & ~3;
    const int* __restrict__ cs = g_csr[s] + r;

#define NBA(u) do { \
        int n_ = __ldg(&nd[(u)]); \
        uint4 t_ = __ldg(&tab[(n_ & 0xFFFF) * 8 + l]); \
        __half2 d_ = __half2half2(__ushort_as_half((unsigned short)((unsigned)n_ >> 16))); \
        __half2* th_ = reinterpret_cast<__half2*>(&t_); \
        za0 = __hfma2(th_[0], d_, za0); za1 = __hfma2(th_[1], d_, za1); \
        za2 = __hfma2(th_[2], d_, za2); za3 = __hfma2(th_[3], d_, za3); \
    } while (0)
#define NBB(u) do { \
        int n_ = __ldg(&nd[(u)]); \
        uint4 t_ = __ldg(&tab[(n_ & 0xFFFF) * 8 + l]); \
        __half2 d_ = __half2half2(__ushort_as_half((unsigned short)((unsigned)n_ >> 16))); \
        __half2* th_ = reinterpret_cast<__half2*>(&t_); \
        zb0 = __hfma2(th_[0], d_, zb0); zb1 = __hfma2(th_[1], d_, zb1); \
        zb2 = __hfma2(th_[2], d_, zb2); zb3 = __hfma2(th_[3], d_, zb3); \
    } while (0)

    for (int k = 0; k < dpad; k += 4) {
        int4 q = __ldg((const int4*)(cs + k));
        NBA(q.x); NBB(q.y); NBA(q.z); NBB(q.w);
    }
#undef NBA
#undef NBB

    float2 f0 = __half22float2(__hadd2(za0, zb0));
    float2 f1 = __half22float2(__hadd2(za1, zb1));
    float2 f2 = __half22float2(__hadd2(za2, zb2));
    float2 f3 = __half22float2(__hadd2(za3, zb3));

    const float* b1 = s ? b1C : b1A;
    float4 b0 = ldg4(b1 + l * 8), b1v = ldg4(b1 + l * 8 + 4);
    float x0 = dv * fmaxf(fmaf(dv, f0.x, b0.x), 0.f);
    float x1 = dv * fmaxf(fmaf(dv, f0.y, b0.y), 0.f);
    float x2 = dv * fmaxf(fmaf(dv, f1.x, b0.z), 0.f);
    float x3 = dv * fmaxf(fmaf(dv, f1.y, b0.w), 0.f);
    float x4 = dv * fmaxf(fmaf(dv, f2.x, b1v.x), 0.f);
    float x5 = dv * fmaxf(fmaf(dv, f2.y, b1v.y), 0.f);
    float x6 = dv * fmaxf(fmaf(dv, f3.x, b1v.z), 0.f);
    float x7 = dv * fmaxf(fmaf(dv, f3.y, b1v.w), 0.f);
    __half2 h0 = __floats2half2_rn(x0, x1);
    __half2 h1 = __floats2half2_rn(x2, x3);
    __half2 h2 = __floats2half2_rn(x4, x5);
    __half2 h3 = __floats2half2_rn(x6, x7);
    uint4 u;
    u.x = *reinterpret_cast<unsigned int*>(&h0);
    u.y = *reinterpret_cast<unsigned int*>(&h1);
    u.z = *reinterpret_cast<unsigned int*>(&h2);
    u.w = *reinterpret_cast<unsigned int*>(&h3);
    g_x[s][v * 8 + l] = u;
}

// launch 5: pull layer 2 + segmented pooling (HADD2, 8-then-4-wide, no tail) +
// re-zero this block's g_deg entries for the next call.
__global__ void __launch_bounds__(256) k_pull2(const int* __restrict__ batchA,
                                               const int* __restrict__ batchC) {
    int blk = blockIdx.x;              // 6250 blocks: 3125 per graph
    int s = blk >= 3125;
    int v0 = (blk - s * 3125) * 32;
    int li = threadIdx.x >> 3;         // local node 0..31
    int l  = threadIdx.x & 7;          // feature chunk 0..7
    int v = v0 + li;

    const uint4* __restrict__ xd4 = (const uint4*)g_x[s];
    __half2 z = __float2half2_rn(0.f);
    __half2 ha0 = z, ha1 = z, ha2 = z, ha3 = z;
    __half2 hb0 = z, hb1 = z, hb2 = z, hb3 = z;

#define ACCA(q) do { __half2* h_ = reinterpret_cast<__half2*>(&(q)); \
        ha0 = __hadd2(ha0, h_[0]); ha1 = __hadd2(ha1, h_[1]); \
        ha2 = __hadd2(ha2, h_[2]); ha3 = __hadd2(ha3, h_[3]); } while (0)
#define ACCB(q) do { __half2* h_ = reinterpret_cast<__half2*>(&(q)); \
        hb0 = __hadd2(hb0, h_[0]); hb1 = __hadd2(hb1, h_[1]); \
        hb2 = __hadd2(hb2, h_[2]); hb3 = __hadd2(hb3, h_[3]); } while (0)

    uint4 qs = __ldg(&xd4[v * 8 + l]);   // self term
    ACCA(qs);
    int r = g_rowptr[s][v], d = g_deg[s][v];
    int dpad = (d + 3) & ~3;
    const int* __restrict__ cs = g_csr[s] + r;
    int k = 0;
    for (; k + 8 <= dpad; k += 8) {
        int4 qa = __ldg((const int4*)(cs + k));
        int4 qb = __ldg((const int4*)(cs + k + 4));
        uint4 q0 = __ldg(&xd4[qa.x * 8 + l]);
        uint4 q1 = __ldg(&xd4[qa.y * 8 + l]);
        uint4 q2 = __ldg(&xd4[qa.z * 8 + l]);
        uint4 q3 = __ldg(&xd4[qa.w * 8 + l]);
        uint4 q4 = __ldg(&xd4[qb.x * 8 + l]);
        uint4 q5 = __ldg(&xd4[qb.y * 8 + l]);
        uint4 q6 = __ldg(&xd4[qb.z * 8 + l]);
        uint4 q7 = __ldg(&xd4[qb.w * 8 + l]);
        ACCA(q0); ACCB(q1); ACCA(q2); ACCB(q3);
        ACCA(q4); ACCB(q5); ACCA(q6); ACCB(q7);
    }
    if (k < dpad) {   // exactly one 4-wide batch remains (dpad % 8 == 4)
        int4 q = __ldg((const int4*)(cs + k));
        uint4 q0 = __ldg(&xd4[q.x * 8 + l]);
        uint4 q1 = __ldg(&xd4[q.y * 8 + l]);
        uint4 q2 = __ldg(&xd4[q.z * 8 + l]);
        uint4 q3 = __ldg(&xd4[q.w * 8 + l]);
        ACCA(q0); ACCB(q1); ACCA(q2); ACCB(q3);
    }
#undef ACCA
#undef ACCB

    float2 p0 = __half22float2(__hadd2(ha0, hb0));
    float2 p1 = __half22float2(__hadd2(ha1, hb1));
    float2 p2 = __half22float2(__hadd2(ha2, hb2));
    float2 p3 = __half22float2(__hadd2(ha3, hb3));
    float dv = __ldg(&g_dinv[s][v]);

    __shared__ float sp[32][68];   // padded to break bank conflicts
    __shared__ int   sb[32];
    sp[li][l * 8 + 0] = p0.x * dv; sp[li][l * 8 + 1] = p0.y * dv;
    sp[li][l * 8 + 2] = p1.x * dv; sp[li][l * 8 + 3] = p1.y * dv;
    sp[li][l * 8 + 4] = p2.x * dv; sp[li][l * 8 + 5] = p2.y * dv;
    sp[li][l * 8 + 6] = p3.x * dv; sp[li][l * 8 + 7] = p3.y * dv;
    if (threadIdx.x < 32)
        sb[threadIdx.x] = __ldg((s ? batchC : batchA) + v0 + threadIdx.x);
    __syncthreads();

    // all reads of g_deg for this block's nodes are done -> re-zero for next call
    if (threadIdx.x < 32) g_deg[s][v0 + threadIdx.x] = 0;

    int gId = sb[li];
    bool head = (li == 0) || (sb[li - 1] != gId);
    if (head) {
        int len = 1;
        while (li + len < 32 && sb[li + len] == gId) len++;
        float t0 = 0, t1 = 0, t2 = 0, t3 = 0, t4 = 0, t5 = 0, t6 = 0, t7 = 0;
        for (int j = li; j < li + len; j++) {
            t0 += sp[j][l * 8 + 0]; t1 += sp[j][l * 8 + 1];
            t2 += sp[j][l * 8 + 2]; t3 += sp[j][l * 8 + 3];
            t4 += sp[j][l * 8 + 4]; t5 += sp[j][l * 8 + 5];
            t6 += sp[j][l * 8 + 6]; t7 += sp[j][l * 8 + 7];
        }
        float* dst = (float*)&g_pool[s][gId * 16];
        red_add_v4(dst + l * 8,     make_float4(t0, t1, t2, t3));
        red_add_v4(dst + l * 8 + 4, make_float4(t4, t5, t6, t7));
    }
}

// count of nodes with batch==g in sorted array (two binary searches)
__device__ __forceinline__ int cnt_graph(const int* __restrict__ b, int g) {
    int lo = 0, hi = NMAX;
    while (lo < hi) { int m = (lo + hi) >> 1; if (__ldg(b + m) < g) lo = m + 1; else hi = m; }
    int lb = lo;
    lo = 0; hi = NMAX;
    while (lo < hi) { int m = (lo + hi) >> 1; if (__ldg(b + m) <= g) lo = m + 1; else hi = m; }
    return lo - lb;
}

// launch 6: epilogue (8 graphs/block, 16 lanes x 4 cols) + re-zero pool.
__global__ void __launch_bounds__(128) k_epilogue(
    const float* __restrict__ sem,
    const int* __restrict__ batchA, const int* __restrict__ batchC,
    const float* __restrict__ W2A, const float* __restrict__ b2A,
    const float* __restrict__ W2C, const float* __restrict__ b2C,
    const float* __restrict__ Wg1, const float* __restrict__ bg1,
    const float* __restrict__ Wsem, const float* __restrict__ bsem,
    const float* __restrict__ Wg2, const float* __restrict__ bg2,
    const float* __restrict__ ln_g, const float* __restrict__ ln_b,
    const float* __restrict__ Wc, const float* __restrict__ bc,
    float* __restrict__ out) {
    int sg = threadIdx.x >> 4;     // subgroup 0..7 (one graph each)
    int l  = threadIdx.x & 15;
    int g  = blockIdx.x * 8 + sg;
    int j0 = l * 4;

    __shared__ float sPA[8][64], sPC[8][64];
    __shared__ float sA [8][64], sB [8][64];
    __shared__ float sHS[8][64], sHM[8][64];

    float4 PA = g_pool[0][g * 16 + l];
    float4 PC = g_pool[1][g * 16 + l];
    g_pool[0][g * 16 + l] = make_float4(0.f, 0.f, 0.f, 0.f);   // restore for next call
    g_pool[1][g * 16 + l] = make_float4(0.f, 0.f, 0.f, 0.f);
    *(float4*)&sPA[sg][j0] = PA;
    *(float4*)&sPC[sg][j0] = PC;
    float cntA = (float)cnt_graph(batchA, g);
    float cntC = (float)cnt_graph(batchC, g);
    __syncwarp();

    float4 a = make_float4(0.f, 0.f, 0.f, 0.f);
    float4 b = make_float4(0.f, 0.f, 0.f, 0.f);
#pragma unroll 4
    for (int k = 0; k < 64; k++) {
        float pa = sPA[sg][k], pc = sPC[sg][k];
        float4 wa = ldg4(W2A + k * 64 + j0);
        float4 wc = ldg4(W2C + k * 64 + j0);
        a.x = fmaf(pa, wa.x, a.x); a.y = fmaf(pa, wa.y, a.y);
        a.z = fmaf(pa, wa.z, a.z); a.w = fmaf(pa, wa.w, a.w);
        b.x = fmaf(pc, wc.x, b.x); b.y = fmaf(pc, wc.y, b.y);
        b.z = fmaf(pc, wc.z, b.z); b.w = fmaf(pc, wc.w, b.w);
    }
    {
        float4 ba = ldg4(b2A + j0), bb = ldg4(b2C + j0);
        a.x = fmaf(cntA, ba.x, a.x); a.y = fmaf(cntA, ba.y, a.y);
        a.z = fmaf(cntA, ba.z, a.z); a.w = fmaf(cntA, ba.w, a.w);
        b.x = fmaf(cntC, bb.x, b.x); b.y = fmaf(cntC, bb.y, b.y);
        b.z = fmaf(cntC, bb.z, b.z); b.w = fmaf(cntC, bb.w, b.w);
    }
    *(float4*)&sA[sg][j0] = a;
    *(float4*)&sB[sg][j0] = b;
    __syncwarp();

    // gate 1
    float4 acc = ldg4(bg1 + j0);
#pragma unroll 4
    for (int k = 0; k < 64; k++) {
        float va = sA[sg][k];
        float4 w = ldg4(Wg1 + k * 64 + j0);
        acc.x = fmaf(va, w.x, acc.x); acc.y = fmaf(va, w.y, acc.y);
        acc.z = fmaf(va, w.z, acc.z); acc.w = fmaf(va, w.w, acc.w);
    }
#pragma unroll 4
    for (int k = 0; k < 64; k++) {
        float vb = sB[sg][k];
        float4 w = ldg4(Wg1 + (64 + k) * 64 + j0);
        acc.x = fmaf(vb, w.x, acc.x); acc.y = fmaf(vb, w.y, acc.y);
        acc.z = fmaf(vb, w.z, acc.z); acc.w = fmaf(vb, w.w, acc.w);
    }
    float4 g1;
    g1.x = 1.f / (1.f + expf(-acc.x));
    g1.y = 1.f / (1.f + expf(-acc.y));
    g1.z = 1.f / (1.f + expf(-acc.z));
    g1.w = 1.f / (1.f + expf(-acc.w));
    float4 hst;
    hst.x = g1.x * a.x + (1.f - g1.x) * b.x;
    hst.y = g1.y * a.y + (1.f - g1.y) * b.y;
    hst.z = g1.z * a.z + (1.f - g1.z) * b.z;
    hst.w = g1.w * a.w + (1.f - g1.w) * b.w;

    // sem projection
    float4 ac2 = ldg4(bsem + j0);
    const float* semrow = sem + g * SEM;
#pragma unroll 4
    for (int k = 0; k < SEM; k += 4) {
        float4 s4 = ldg4(semrow + k);
        float4 w0 = ldg4(Wsem + (k + 0) * 64 + j0);
        float4 w1 = ldg4(Wsem + (k + 1) * 64 + j0);
        float4 w2 = ldg4(Wsem + (k + 2) * 64 + j0);
        float4 w3 = ldg4(Wsem + (k + 3) * 64 + j0);
        ac2.x = fmaf(s4.x, w0.x, ac2.x); ac2.y = fmaf(s4.x, w0.y, ac2.y);
        ac2.z = fmaf(s4.x, w0.z, ac2.z); ac2.w = fmaf(s4.x, w0.w, ac2.w);
        ac2.x = fmaf(s4.y, w1.x, ac2.x); ac2.y = fmaf(s4.y, w1.y, ac2.y);
        ac2.z = fmaf(s4.y, w1.z, ac2.z); ac2.w = fmaf(s4.y, w1.w, ac2.w);
        ac2.x = fmaf(s4.z, w2.x, ac2.x); ac2.y = fmaf(s4.z, w2.y, ac2.y);
        ac2.z = fmaf(s4.z, w2.z, ac2.z); ac2.w = fmaf(s4.z, w2.w, ac2.w);
        ac2.x = fmaf(s4.w, w3.x, ac2.x); ac2.y = fmaf(s4.w, w3.y, ac2.y);
        ac2.z = fmaf(s4.w, w3.z, ac2.z); ac2.w = fmaf(s4.w, w3.w, ac2.w);
    }
    float4 hm;
    hm.x = fmaxf(ac2.x, 0.f); hm.y = fmaxf(ac2.y, 0.f);
    hm.z = fmaxf(ac2.z, 0.f); hm.w = fmaxf(ac2.w, 0.f);

    *(float4*)&sHS[sg][j0] = hst;
    *(float4*)&sHM[sg][j0] = hm;
    __syncwarp();

    // gate 2
    float4 ac3 = ldg4(bg2 + j0);
#pragma unroll 4
    for (int k = 0; k < 64; k++) {
        float vh = sHS[sg][k];
        float4 w = ldg4(Wg2 + k * 64 + j0);
        ac3.x = fmaf(vh, w.x, ac3.x); ac3.y = fmaf(vh, w.y, ac3.y);
        ac3.z = fmaf(vh, w.z, ac3.z); ac3.w = fmaf(vh, w.w, ac3.w);
    }
#pragma unroll 4
    for (int k = 0; k < 64; k++) {
        float vm = sHM[sg][k];
        float4 w = ldg4(Wg2 + (64 + k) * 64 + j0);
        ac3.x = fmaf(vm, w.x, ac3.x); ac3.y = fmaf(vm, w.y, ac3.y);
        ac3.z = fmaf(vm, w.z, ac3.z); ac3.w = fmaf(vm, w.w, ac3.w);
    }
    float4 g2;
    g2.x = 1.f / (1.f + expf(-ac3.x));
    g2.y = 1.f / (1.f + expf(-ac3.y));
    g2.z = 1.f / (1.f + expf(-ac3.z));
    g2.w = 1.f / (1.f + expf(-ac3.w));
    float4 h;
    h.x = g2.x * hst.x + (1.f - g2.x) * hm.x;
    h.y = g2.y * hst.y + (1.f - g2.y) * hm.y;
    h.z = g2.z * hst.z + (1.f - g2.z) * hm.z;
    h.w = g2.w * hst.w + (1.f - g2.w) * hm.w;

    // layernorm over 64 (16-lane shfl reduce)
    float s1 = (h.x + h.y) + (h.z + h.w);
    float s2 = (h.x * h.x + h.y * h.y) + (h.z * h.z + h.w * h.w);
#pragma unroll
    for (int m = 1; m < 16; m <<= 1) {
        s1 += __shfl_xor_sync(0xFFFFFFFFu, s1, m);
        s2 += __shfl_xor_sync(0xFFFFFFFFu, s2, m);
    }
    float mu  = s1 * (1.f / 64.f);
    float var = s2 * (1.f / 64.f) - mu * mu;
    float rstd = rsqrtf(var + 1e-5f);
    float4 lg = ldg4(ln_g + j0), lb = ldg4(ln_b + j0);
    float4 hn;
    hn.x = (h.x - mu) * rstd * lg.x + lb.x;
    hn.y = (h.y - mu) * rstd * lg.y + lb.y;
    hn.z = (h.z - mu) * rstd * lg.z + lb.z;
    hn.w = (h.w - mu) * rstd * lg.w + lb.w;

    // classifier (NCLS=2): Wc is [64,2]
    float4 wc0 = ldg4(Wc + j0 * 2);
    float4 wc1 = ldg4(Wc + j0 * 2 + 4);
    float o0 = hn.x * wc0.x + hn.y * wc0.z + hn.z * wc1.x + hn.w * wc1.z;
    float o1 = hn.x * wc0.y + hn.y * wc0.w + hn.z * wc1.y + hn.w * wc1.w;
#pragma unroll
    for (int m = 1; m < 16; m <<= 1) {
        o0 += __shfl_xor_sync(0xFFFFFFFFu, o0, m);
        o1 += __shfl_xor_sync(0xFFFFFFFFu, o1, m);
    }
    if (l == 0) {
        out[g * 2 + 0] = o0 + __ldg(bc + 0);
        out[g * 2 + 1] = o1 + __ldg(bc + 1);
    }
}

// ---------------- launch ----------------
extern "C" void kernel_launch(void* const* d_in, const int* in_sizes, int n_in,
                              void* d_out, int out_size) {
    const int*   ast_type  = (const int*)  d_in[0];
    const int*   ast_edge  = (const int*)  d_in[1];
    const int*   ast_batch = (const int*)  d_in[2];
    const int*   cfg_type  = (const int*)  d_in[3];
    const int*   cfg_edge  = (const int*)  d_in[4];
    const int*   cfg_batch = (const int*)  d_in[5];
    const float* sem       = (const float*)d_in[6];
    const float* ast_emb   = (const float*)d_in[7];
    const float* cfg_emb   = (const float*)d_in[8];
    const float* ast_W1    = (const float*)d_in[9];
    const float* ast_b1    = (const float*)d_in[10];
    const float* ast_W2    = (const float*)d_in[11];
    const float* ast_b2    = (const float*)d_in[12];
    const float* cfg_W1    = (const float*)d_in[13];
    const float* cfg_b1    = (const float*)d_in[14];
    const float* cfg_W2    = (const float*)d_in[15];
    const float* cfg_b2    = (const float*)d_in[16];
    const float* Wg1       = (const float*)d_in[17];
    const float* bg1       = (const float*)d_in[18];
    const float* Wsem      = (const float*)d_in[19];
    const float* bsem      = (const float*)d_in[20];
    const float* Wg2       = (const float*)d_in[21];
    const float* bg2       = (const float*)d_in[22];
    const float* ln_g      = (const float*)d_in[23];
    const float* ln_b      = (const float*)d_in[24];
    const float* Wc        = (const float*)d_in[25];
    const float* bc        = (const float*)d_in[26];
    float* out = (float*)d_out;

    k_degtab<<<DEGB8 + 75, 256>>>(ast_edge, cfg_edge,
                                  ast_emb, ast_W1, cfg_emb, cfg_W1);
    k_scan<<<2 * SCAN_NB, SCAN_B>>>(ast_type, cfg_type);
    k_fill<<<DEGB8, 256>>>(ast_edge, cfg_edge);

    k_pull1<<<2 * NMAX / 32, 256>>>(ast_b1, cfg_b1);   // <- ncu capture slot 4
    k_pull2<<<2 * NMAX / 32, 256>>>(ast_batch, cfg_batch);

    k_epilogue<<<NG / 8, 128>>>(sem, ast_batch, cfg_batch,
                                ast_W2, ast_b2, cfg_W2, cfg_b2,
                                Wg1, bg1, Wsem, bsem, Wg2, bg2,
                                ln_g, ln_b, Wc, bc, out);
}